// round 16
// baseline (speedup 1.0000x reference)
#include <cuda_runtime.h>
#include <cuda_fp16.h>
#include <math.h>
#include <stdint.h>

// ---------------- scratch (static device globals; no allocation) ----------------
__device__ float g_col[33554432];
__device__ float g_off[19267584];
__device__ float g_tmp[8388608];
__device__ float g_a[2097152];
__device__ float g_b[2097152];
__device__ float g_mean[512];
__device__ float g_rstd[512];
__device__ float g_wpad[33760];
__device__ float g_psum[262144];
__device__ float g_psum2[262144];

#define MAXCOL 512

// ---------------- deformable sampling -> col matrix (4 px/thread, channel-chunked) ----------------
__global__ void deform_sample_kernel(const float* __restrict__ x,
                                     const float* __restrict__ off,
                                     float* __restrict__ col,
                                     int Cin, int cchunk, int nChunk,
                                     int H, int W, int KH, int KW,
                                     int stride, int pad, int Ho, int Wo)
{
    int npix = Ho * Wo;
    int pix0 = (blockIdx.x * blockDim.x + threadIdx.x) * 4;
    if (pix0 >= npix) return;
    int K = KH * KW;
    int k = blockIdx.y;
    int n = blockIdx.z / nChunk;
    int c0 = (blockIdx.z % nChunk) * cchunk;

    const float* offn = off + (size_t)n * 3 * K * npix;
    float4 oy4 = *(const float4*)(offn + (size_t)k * npix + pix0);
    float4 ox4 = *(const float4*)(offn + (size_t)(K + k) * npix + pix0);
    float4 ml4 = *(const float4*)(offn + (size_t)(2 * K + k) * npix + pix0);
    float oys[4] = {oy4.x, oy4.y, oy4.z, oy4.w};
    float oxs[4] = {ox4.x, ox4.y, ox4.z, ox4.w};
    float mls[4] = {ml4.x, ml4.y, ml4.z, ml4.w};

    int ky = k / KW, kx = k % KW;
    float w00[4], w01[4], w10[4], w11[4];
    int b00[4], b01[4], b10[4], b11[4];
#pragma unroll
    for (int i = 0; i < 4; i++) {
        int pix = pix0 + i;
        int ho = pix / Wo, wo = pix % Wo;
        float m = 1.0f / (1.0f + expf(-mls[i]));
        float py = (float)(ho * stride - pad + ky) + oys[i];
        float px = (float)(wo * stride - pad + kx) + oxs[i];
        float y0f = floorf(py), x0f = floorf(px);
        int y0 = (int)y0f, x0 = (int)x0f;
        float wy = py - y0f, wx = px - x0f;
        int y1 = y0 + 1, x1 = x0 + 1;
        float vy0 = (y0 >= 0 && y0 <= H - 1) ? 1.0f : 0.0f;
        float vy1 = (y1 >= 0 && y1 <= H - 1) ? 1.0f : 0.0f;
        float vx0 = (x0 >= 0 && x0 <= W - 1) ? 1.0f : 0.0f;
        float vx1 = (x1 >= 0 && x1 <= W - 1) ? 1.0f : 0.0f;
        int y0c = min(max(y0, 0), H - 1), y1c = min(max(y1, 0), H - 1);
        int x0c = min(max(x0, 0), W - 1), x1c = min(max(x1, 0), W - 1);
        w00[i] = (1.0f - wy) * (1.0f - wx) * vy0 * vx0 * m;
        w01[i] = (1.0f - wy) * wx          * vy0 * vx1 * m;
        w10[i] = wy          * (1.0f - wx) * vy1 * vx0 * m;
        w11[i] = wy          * wx          * vy1 * vx1 * m;
        b00[i] = y0c * W + x0c;
        b01[i] = y0c * W + x1c;
        b10[i] = y1c * W + x0c;
        b11[i] = y1c * W + x1c;
    }

    const float* xn = x + (size_t)n * Cin * H * W;
    float* cp = col + (size_t)n * Cin * K * npix + (size_t)k * npix + pix0;
    size_t cstride = (size_t)K * npix;
    int cend = min(c0 + cchunk, Cin);
    for (int c = c0; c < cend; c++) {
        const float* xc = xn + (size_t)c * H * W;
        float4 v;
        v.x = w00[0] * __ldg(xc + b00[0]) + w01[0] * __ldg(xc + b01[0])
            + w10[0] * __ldg(xc + b10[0]) + w11[0] * __ldg(xc + b11[0]);
        v.y = w00[1] * __ldg(xc + b00[1]) + w01[1] * __ldg(xc + b01[1])
            + w10[1] * __ldg(xc + b10[1]) + w11[1] * __ldg(xc + b11[1]);
        v.z = w00[2] * __ldg(xc + b00[2]) + w01[2] * __ldg(xc + b01[2])
            + w10[2] * __ldg(xc + b10[2]) + w11[2] * __ldg(xc + b11[2]);
        v.w = w00[3] * __ldg(xc + b00[3]) + w01[3] * __ldg(xc + b01[3])
            + w10[3] * __ldg(xc + b10[3]) + w11[3] * __ldg(xc + b11[3]);
        *(float4*)(cp + (size_t)c * cstride) = v;
    }
}

// ---------------- fused stage-1 weight padding (off1 + dcn1, K=147 -> lda=160) ----------------
__global__ void pad_weights2_kernel(const float* __restrict__ w1, float* __restrict__ wp1, int M1,
                                    const float* __restrict__ w2, float* __restrict__ wp2, int M2,
                                    int K, int Kp)
{
    int idx = blockIdx.x * blockDim.x + threadIdx.x;
    int total1 = M1 * Kp;
    if (idx < total1) {
        int m = idx / Kp, k = idx % Kp;
        wp1[idx] = (k < K) ? w1[m * K + k] : 0.0f;
        return;
    }
    idx -= total1;
    if (idx < M2 * Kp) {
        int m = idx / Kp, k = idx % Kp;
        wp2[idx] = (k < K) ? w2[m * K + k] : 0.0f;
    }
}

// ---------------- fp16x3 implicit-conv / GEMM kernel (pre-split smem) ----------------
// MODE 0: B = col matrix;  MODE 1: implicit zero-pad conv;  MODE 2: reflect-pad (BNORM option)
struct ConvGeom { int Cin, H, W, KH, KW, KKW, stride, pad, Wo; };

__device__ __forceinline__ void split_h2(float a, float b, uint32_t& hi, uint32_t& lo) {
    __half ha = __float2half_rn(a), hb = __float2half_rn(b);
    float ra = a - __half2float(ha), rb = b - __half2float(hb);
    __half2 H = __halves2half2(ha, hb);
    __half2 L = __halves2half2(__float2half_rn(ra), __float2half_rn(rb));
    hi = *reinterpret_cast<uint32_t*>(&H);
    lo = *reinterpret_cast<uint32_t*>(&L);
}

#define AS2_STRIDE 20
#define BS2_STRIDE 136
#define BS2_BUF (16 * BS2_STRIDE)

extern __shared__ float smem_dyn[];

#define MMA_F16(acc, a0, a1, a2, a3, b0, b1)                                   \
    asm volatile(                                                              \
        "mma.sync.aligned.m16n8k16.row.col.f32.f16.f16.f32 "                   \
        "{%0,%1,%2,%3}, {%4,%5,%6,%7}, {%8,%9}, {%0,%1,%2,%3};\n"              \
        : "+f"(acc[0]), "+f"(acc[1]), "+f"(acc[2]), "+f"(acc[3])               \
        : "r"(a0), "r"(a1), "r"(a2), "r"(a3), "r"(b0), "r"(b1))

template <int BM, int MODE, bool STATS, bool BNORM>
__global__ void __launch_bounds__(256, (BM == 64) ? 2 : 1)
gemm_conv_kernel(const float* __restrict__ A, int lda,
                 const float* __restrict__ B,
                 const float* __restrict__ bias,
                 float* __restrict__ C,
                 int M, int Kd, int N, ConvGeom g,
                 float* __restrict__ psum, float* __restrict__ psum2,
                 const float* __restrict__ nmean, const float* __restrict__ nrstd)
{
    constexpr int AS2_BUF = BM * AS2_STRIDE;
    constexpr int IMAX = BM / 32;
    constexpr int ACP = BM / 32;
    uint32_t* AsH = (uint32_t*)smem_dyn;
    uint32_t* AsL = AsH + 2 * AS2_BUF;
    uint32_t* BsH = AsL + 2 * AS2_BUF;
    uint32_t* BsL = BsH + 2 * BS2_BUF;
    constexpr int SW = STATS ? 4 : 1;
    __shared__ float s_sum[SW][BM][2];

    int nb = blockIdx.z;
    float* Cn = C + (size_t)nb * M * N;
    int bm = blockIdx.y * BM, bn = blockIdx.x * 128;
    int tid = threadIdx.x;
    int wid = tid >> 5, lane = tid & 31;
    int warp_m = (wid >> 2) * (BM / 2);
    int warp_n = (wid & 3) * 32;
    int lr = lane >> 2, lc = lane & 3;

    float acc[IMAX][4][4];
#pragma unroll
    for (int i = 0; i < IMAX; i++)
#pragma unroll
        for (int j = 0; j < 4; j++)
#pragma unroll
            for (int q = 0; q < 4; q++) acc[i][j][q] = 0.0f;

    int nk = (Kd + 31) / 32;

    auto loadA = [&](int kt, float4* apref) {
        int k0 = kt * 32;
#pragma unroll
        for (int t = 0; t < ACP; t++) {
            int idx = tid + t * 256;
            int m = idx >> 3;
            int k4 = (idx & 7) << 2;
            int gm = bm + m;
            if (gm < M) apref[t] = *(const float4*)(A + (size_t)gm * lda + k0 + k4);
            else        apref[t] = make_float4(0.f, 0.f, 0.f, 0.f);
        }
    };
    auto stsA = [&](const float4* apref, int s) {
        uint32_t* dH = AsH + s * AS2_BUF;
        uint32_t* dL = AsL + s * AS2_BUF;
#pragma unroll
        for (int t = 0; t < ACP; t++) {
            int idx = tid + t * 256;
            int m = idx >> 3;
            int kp = (idx & 7) << 1;
            uint32_t h0, l0, h1, l1;
            split_h2(apref[t].x, apref[t].y, h0, l0);
            split_h2(apref[t].z, apref[t].w, h1, l1);
            dH[m * AS2_STRIDE + kp] = h0; dH[m * AS2_STRIDE + kp + 1] = h1;
            dL[m * AS2_STRIDE + kp] = l0; dL[m * AS2_STRIDE + kp + 1] = l1;
        }
    };

    int kp_t = tid >> 4;
    int cb_t = (tid & 15) << 3;

    auto loadB_col = [&](int kt, float* r0, float* r1) {
        const float* Bn = B + (size_t)nb * Kd * N;
        int gk0 = kt * 32 + 2 * kp_t;
        int gk1 = gk0 + 1;
        if (gk0 < Kd) {
            float4 a = *(const float4*)(Bn + (size_t)gk0 * N + bn + cb_t);
            float4 b = *(const float4*)(Bn + (size_t)gk0 * N + bn + cb_t + 4);
            r0[0]=a.x; r0[1]=a.y; r0[2]=a.z; r0[3]=a.w; r0[4]=b.x; r0[5]=b.y; r0[6]=b.z; r0[7]=b.w;
        } else { for (int i = 0; i < 8; i++) r0[i] = 0.0f; }
        if (gk1 < Kd) {
            float4 a = *(const float4*)(Bn + (size_t)gk1 * N + bn + cb_t);
            float4 b = *(const float4*)(Bn + (size_t)gk1 * N + bn + cb_t + 4);
            r1[0]=a.x; r1[1]=a.y; r1[2]=a.z; r1[3]=a.w; r1[4]=b.x; r1[5]=b.y; r1[6]=b.z; r1[7]=b.w;
        } else { for (int i = 0; i < 8; i++) r1[i] = 0.0f; }
    };

    auto gatherB_row = [&](int gk, float* r) {
        bool kv = gk < Kd;
        int kk = kv ? gk : 0;
        int c = kk / g.KKW;
        int rr = kk - c * g.KKW;
        int ky = rr / g.KW;
        int kx = rr - ky * g.KW;
        int pix = bn + cb_t;
        int ho = pix / g.Wo;
        int wo = pix - ho * g.Wo;
        int iy = ho * g.stride - g.pad + ky;
        int ix0 = wo * g.stride - g.pad + kx;
        const float* xc = B + ((size_t)nb * g.Cin + c) * g.H * g.W;
        if (MODE == 2) {
            float mnv = 0.0f, rsv = 1.0f;
            if (BNORM) {
                mnv = __ldg(nmean + nb * g.Cin + c);
                rsv = __ldg(nrstd + nb * g.Cin + c);
            }
            if (iy < 0) iy = -iy; else if (iy >= g.H) iy = 2 * g.H - 2 - iy;
            const float* rowp = xc + (size_t)iy * g.W;
#pragma unroll
            for (int i = 0; i < 8; i++) {
                int ix = ix0 + i * g.stride;
                if (ix < 0) ix = -ix; else if (ix >= g.W) ix = 2 * g.W - 2 - ix;
                float v = kv ? __ldg(rowp + ix) : 0.0f;
                if (BNORM) v = fmaxf((v - mnv) * rsv, 0.0f);
                r[i] = v;
            }
        } else {
            bool rok = kv && iy >= 0 && iy < g.H;
            const float* rowp = xc + (size_t)max(iy, 0) * g.W;
#pragma unroll
            for (int i = 0; i < 8; i++) {
                int ix = ix0 + i * g.stride;
                r[i] = (rok && ix >= 0 && ix < g.W) ? __ldg(rowp + ix) : 0.0f;
            }
        }
    };
    auto loadB = [&](int kt, float* r0, float* r1) {
        if (MODE == 0) { loadB_col(kt, r0, r1); }
        else {
            int gk0 = kt * 32 + 2 * kp_t;
            gatherB_row(gk0, r0);
            gatherB_row(gk0 + 1, r1);
        }
    };
    auto stsB = [&](const float* r0, const float* r1, int s) {
        uint32_t* dH = BsH + s * BS2_BUF + kp_t * BS2_STRIDE + cb_t;
        uint32_t* dL = BsL + s * BS2_BUF + kp_t * BS2_STRIDE + cb_t;
#pragma unroll
        for (int i = 0; i < 8; i++) {
            uint32_t h, l;
            split_h2(r0[i], r1[i], h, l);
            dH[i] = h; dL[i] = l;
        }
    };

    float4 apref[ACP];
    float br0[8], br1[8];
    loadA(0, apref);
    loadB(0, br0, br1);
    stsA(apref, 0);
    stsB(br0, br1, 0);
    __syncthreads();

    for (int kt = 0; kt < nk; kt++) {
        int s = kt & 1;
        bool do_pref = (kt + 1 < nk);
        if (do_pref) {
            loadA(kt + 1, apref);
            loadB(kt + 1, br0, br1);
        }

        const uint32_t* AsHb = AsH + s * AS2_BUF;
        const uint32_t* AsLb = AsL + s * AS2_BUF;
        const uint32_t* BsHb = BsH + s * BS2_BUF;
        const uint32_t* BsLb = BsL + s * BS2_BUF;
#pragma unroll
        for (int ks = 0; ks < 2; ks++) {
            uint32_t ah[IMAX][4], al[IMAX][4], bh[4][2], bl[4][2];
#pragma unroll
            for (int i = 0; i < IMAX; i++) {
                int base = (warp_m + i * 16 + lr) * AS2_STRIDE + ks * 8 + lc;
                ah[i][0] = AsHb[base];
                ah[i][1] = AsHb[base + 8 * AS2_STRIDE];
                ah[i][2] = AsHb[base + 4];
                ah[i][3] = AsHb[base + 8 * AS2_STRIDE + 4];
                al[i][0] = AsLb[base];
                al[i][1] = AsLb[base + 8 * AS2_STRIDE];
                al[i][2] = AsLb[base + 4];
                al[i][3] = AsLb[base + 8 * AS2_STRIDE + 4];
            }
#pragma unroll
            for (int j = 0; j < 4; j++) {
                int bbase = (ks * 8 + lc) * BS2_STRIDE + warp_n + j * 8 + lr;
                bh[j][0] = BsHb[bbase];
                bh[j][1] = BsHb[bbase + 4 * BS2_STRIDE];
                bl[j][0] = BsLb[bbase];
                bl[j][1] = BsLb[bbase + 4 * BS2_STRIDE];
            }
#pragma unroll
            for (int i = 0; i < IMAX; i++)
#pragma unroll
                for (int j = 0; j < 4; j++) {
                    MMA_F16(acc[i][j], ah[i][0], ah[i][1], ah[i][2], ah[i][3],
                            bl[j][0], bl[j][1]);
                    MMA_F16(acc[i][j], al[i][0], al[i][1], al[i][2], al[i][3],
                            bh[j][0], bh[j][1]);
                    MMA_F16(acc[i][j], ah[i][0], ah[i][1], ah[i][2], ah[i][3],
                            bh[j][0], bh[j][1]);
                }
        }
        if (do_pref) {
            stsA(apref, s ^ 1);
            stsB(br0, br1, s ^ 1);
        }
        __syncthreads();
    }

#pragma unroll
    for (int i = 0; i < IMAX; i++) {
        int r0l = warp_m + i * 16 + lr;
        int r1l = r0l + 8;
        int gr0 = bm + r0l, gr1 = bm + r1l;
        float bv0 = (gr0 < M) ? bias[gr0] : 0.0f;
        float bv1 = (gr1 < M) ? bias[gr1] : 0.0f;
        float s0 = 0, q0 = 0, s1 = 0, q1 = 0;
#pragma unroll
        for (int j = 0; j < 4; j++) {
            int cidx = bn + warp_n + j * 8 + lc * 2;
            float v0 = acc[i][j][0] + bv0, v1 = acc[i][j][1] + bv0;
            float v2 = acc[i][j][2] + bv1, v3 = acc[i][j][3] + bv1;
            if (gr0 < M) *(float2*)&Cn[(size_t)gr0 * N + cidx] = make_float2(v0, v1);
            if (gr1 < M) *(float2*)&Cn[(size_t)gr1 * N + cidx] = make_float2(v2, v3);
            if (STATS) {
                s0 += v0 + v1; q0 += v0 * v0 + v1 * v1;
                s1 += v2 + v3; q1 += v2 * v2 + v3 * v3;
            }
        }
        if (STATS) {
            s0 += __shfl_xor_sync(0xffffffff, s0, 1); s0 += __shfl_xor_sync(0xffffffff, s0, 2);
            q0 += __shfl_xor_sync(0xffffffff, q0, 1); q0 += __shfl_xor_sync(0xffffffff, q0, 2);
            s1 += __shfl_xor_sync(0xffffffff, s1, 1); s1 += __shfl_xor_sync(0xffffffff, s1, 2);
            q1 += __shfl_xor_sync(0xffffffff, q1, 1); q1 += __shfl_xor_sync(0xffffffff, q1, 2);
            if (lc == 0) {
                s_sum[wid & 3][r0l][0] = s0; s_sum[wid & 3][r0l][1] = q0;
                s_sum[wid & 3][r1l][0] = s1; s_sum[wid & 3][r1l][1] = q1;
            }
        }
    }
    if (STATS) {
        __syncthreads();
        if (tid < BM) {
            int gm = bm + tid;
            if (gm < M) {
                float s = s_sum[0][tid][0] + s_sum[1][tid][0] + s_sum[2][tid][0] + s_sum[3][tid][0];
                float q = s_sum[0][tid][1] + s_sum[1][tid][1] + s_sum[2][tid][1] + s_sum[3][tid][1];
                size_t nc = (size_t)nb * M + gm;
                psum[nc * MAXCOL + blockIdx.x] = s;
                psum2[nc * MAXCOL + blockIdx.x] = q;
            }
        }
    }
}

// ---------------- finalize stats ----------------
__global__ void finalize_stats_kernel(const float* __restrict__ ps,
                                      const float* __restrict__ ps2,
                                      float* __restrict__ mean, float* __restrict__ rstd,
                                      int ncol, int npix)
{
    int nc = blockIdx.x;
    double s = 0.0, s2 = 0.0;
    for (int j = threadIdx.x; j < ncol; j += 128) {
        s += (double)ps[(size_t)nc * MAXCOL + j];
        s2 += (double)ps2[(size_t)nc * MAXCOL + j];
    }
    __shared__ double sh[128], sh2[128];
    sh[threadIdx.x] = s; sh2[threadIdx.x] = s2;
    __syncthreads();
    for (int o = 64; o > 0; o >>= 1) {
        if (threadIdx.x < o) { sh[threadIdx.x] += sh[threadIdx.x + o]; sh2[threadIdx.x] += sh2[threadIdx.x + o]; }
        __syncthreads();
    }
    if (threadIdx.x == 0) {
        double mn = sh[0] / npix;
        double var = sh2[0] / npix - mn * mn;
        mean[nc] = (float)mn;
        rstd[nc] = (float)rsqrt(var + 1e-5);
    }
}

// ---------------- instance norm: apply (float4) ----------------
__global__ void norm_apply_kernel(const float4* __restrict__ x,
                                  const float* __restrict__ mean,
                                  const float* __restrict__ rstd,
                                  const float4* __restrict__ skip,
                                  float4* __restrict__ out,
                                  int npix4, int relu, size_t total4)
{
    size_t i = (size_t)blockIdx.x * blockDim.x + threadIdx.x;
    if (i >= total4) return;
    int nc = (int)(i / (size_t)npix4);
    float mnv = mean[nc], rsv = rstd[nc];
    float4 v = x[i];
    v.x = (v.x - mnv) * rsv; v.y = (v.y - mnv) * rsv;
    v.z = (v.z - mnv) * rsv; v.w = (v.w - mnv) * rsv;
    if (skip) {
        float4 sk = skip[i];
        v.x += sk.x; v.y += sk.y; v.z += sk.z; v.w += sk.w;
    }
    if (relu) {
        v.x = fmaxf(v.x, 0.0f); v.y = fmaxf(v.y, 0.0f);
        v.z = fmaxf(v.z, 0.0f); v.w = fmaxf(v.w, 0.0f);
    }
    out[i] = v;
}

// ---------------- launch ----------------
static inline int smem_for(int BM) { return (4 * BM * AS2_STRIDE + 4 * BS2_BUF) * 4; }

extern "C" void kernel_launch(void* const* d_in, const int* in_sizes, int n_in,
                              void* d_out, int out_size)
{
    (void)in_sizes; (void)n_in; (void)out_size;
    const float* x      = (const float*)d_in[0];
    const float* off1_w = (const float*)d_in[1];
    const float* off1_b = (const float*)d_in[2];
    const float* dcn1_w = (const float*)d_in[3];
    const float* dcn1_b = (const float*)d_in[4];
    const float* off2_w = (const float*)d_in[5];
    const float* off2_b = (const float*)d_in[6];
    const float* dcn2_w = (const float*)d_in[7];
    const float* dcn2_b = (const float*)d_in[8];
    const float* off3_w = (const float*)d_in[9];
    const float* off3_b = (const float*)d_in[10];
    const float* dcn3_w = (const float*)d_in[11];
    const float* dcn3_b = (const float*)d_in[12];
    const float* rb1_w1 = (const float*)d_in[13];
    const float* rb1_b1 = (const float*)d_in[14];
    const float* rb1_w2 = (const float*)d_in[15];
    const float* rb1_b2 = (const float*)d_in[16];
    const float* rb2_w1 = (const float*)d_in[17];
    const float* rb2_b1 = (const float*)d_in[18];
    const float* rb2_w2 = (const float*)d_in[19];
    const float* rb2_b2 = (const float*)d_in[20];

    float* outp  = (float*)d_out;
    float* out_h = outp;
    float* skip1 = outp + 2097152;
    float* skip2 = outp + 2097152 + 8388608;

    float *col, *offb, *tmp, *ga, *gb, *mn, *rs, *wpad, *psum, *psum2;
    cudaGetSymbolAddress((void**)&col,  g_col);
    cudaGetSymbolAddress((void**)&offb, g_off);
    cudaGetSymbolAddress((void**)&tmp,  g_tmp);
    cudaGetSymbolAddress((void**)&ga,   g_a);
    cudaGetSymbolAddress((void**)&gb,   g_b);
    cudaGetSymbolAddress((void**)&mn,   g_mean);
    cudaGetSymbolAddress((void**)&rs,   g_rstd);
    cudaGetSymbolAddress((void**)&wpad, g_wpad);
    cudaGetSymbolAddress((void**)&psum, g_psum);
    cudaGetSymbolAddress((void**)&psum2, g_psum2);
    float* off1p = wpad;
    float* dcn1p = wpad + 147 * 160;

    static bool attr_set = false;
    if (!attr_set) {
        cudaFuncSetAttribute((const void*)gemm_conv_kernel<64, 0, true, false>,   cudaFuncAttributeMaxDynamicSharedMemorySize, smem_for(64));
        cudaFuncSetAttribute((const void*)gemm_conv_kernel<128, 0, true, false>,  cudaFuncAttributeMaxDynamicSharedMemorySize, smem_for(128));
        cudaFuncSetAttribute((const void*)gemm_conv_kernel<64, 1, false, false>,  cudaFuncAttributeMaxDynamicSharedMemorySize, smem_for(64));
        cudaFuncSetAttribute((const void*)gemm_conv_kernel<128, 2, true, false>,  cudaFuncAttributeMaxDynamicSharedMemorySize, smem_for(128));
        cudaFuncSetAttribute((const void*)gemm_conv_kernel<128, 2, true, true>,   cudaFuncAttributeMaxDynamicSharedMemorySize, smem_for(128));
        attr_set = true;
    }

    ConvGeom g0 = {};

    auto dsample = [&](const float* src, const float* off, float* dst, int Cin, int cchunk,
                       int H, int W, int KH, int KW, int s, int p, int Ho, int Wo) {
        int npix4 = Ho * Wo / 4;
        int nChunk = (Cin + cchunk - 1) / cchunk;
        dim3 grid((npix4 + 255) / 256, KH * KW, 2 * nChunk);
        deform_sample_kernel<<<grid, 256>>>(src, off, dst, Cin, cchunk, nChunk,
                                            H, W, KH, KW, s, p, Ho, Wo);
    };
    auto gemm_col = [&](const float* W, int lda, const float* B, const float* bias, float* C,
                        int M, int K, int N) {
        if (M <= 64) {
            dim3 grid(N / 128, 1, 2);
            gemm_conv_kernel<64, 0, true, false><<<grid, 256, smem_for(64)>>>(
                W, lda, B, bias, C, M, K, N, g0, psum, psum2, nullptr, nullptr);
        } else {
            dim3 grid(N / 128, (M + 127) / 128, 2);
            gemm_conv_kernel<128, 0, true, false><<<grid, 256, smem_for(128)>>>(
                W, lda, B, bias, C, M, K, N, g0, psum, psum2, nullptr, nullptr);
        }
    };
    auto conv_zero = [&](const float* W, int lda, const float* X, const float* bias, float* C,
                         int M, int K, int N, ConvGeom g) {
        dim3 grid(N / 128, (M + 63) / 64, 2);
        gemm_conv_kernel<64, 1, false, false><<<grid, 256, smem_for(64)>>>(
            W, lda, X, bias, C, M, K, N, g, nullptr, nullptr, nullptr, nullptr);
    };
    auto conv_refl = [&](const float* W, int lda, const float* X, const float* bias, float* C,
                         int M, int K, int N, ConvGeom g, bool bnorm) {
        dim3 grid(N / 128, (M + 127) / 128, 2);
        if (bnorm)
            gemm_conv_kernel<128, 2, true, true><<<grid, 256, smem_for(128)>>>(
                W, lda, X, bias, C, M, K, N, g, psum, psum2, mn, rs);
        else
            gemm_conv_kernel<128, 2, true, false><<<grid, 256, smem_for(128)>>>(
                W, lda, X, bias, C, M, K, N, g, psum, psum2, nullptr, nullptr);
    };
    auto fstats = [&](int C, int npix, int ncol) {
        finalize_stats_kernel<<<2 * C, 128>>>(psum, psum2, mn, rs, ncol, npix);
    };
    auto napply = [&](const float* xin, float* dst, int C, int npix,
                      const float* skip, int relu) {
        size_t total4 = (size_t)2 * C * npix / 4;
        norm_apply_kernel<<<(unsigned)((total4 + 255) / 256), 256>>>(
            (const float4*)xin, mn, rs, (const float4*)skip, (float4*)dst, npix / 4, relu, total4);
    };

    // pack stage-1 weights (fused: off1 + dcn1, K=147 -> lda=160)
    pad_weights2_kernel<<<((147 + 64) * 160 + 255) / 256, 256>>>(
        off1_w, off1p, 147, dcn1_w, dcn1p, 64, 147, 160);

    // ===== Stage 1: mdcp(x, 7x7, s1, p3), 3 -> 64, 256x256 =====
    ConvGeom g1 = {3, 256, 256, 7, 7, 49, 1, 3, 256};
    conv_zero(off1p, 160, x, off1_b, offb, 147, 147, 65536, g1);
    dsample(x, offb, col, 3, 3, 256, 256, 7, 7, 1, 3, 256, 256);
    gemm_col(dcn1p, 160, col, dcn1_b, tmp, 64, 147, 65536);
    fstats(64, 65536, 512);
    napply(tmp, skip1, 64, 65536, nullptr, 1);

    // ===== Stage 2: mdcp(h1, 4x4, s2, p1), 64 -> 128, 128x128 =====
    ConvGeom g2 = {64, 256, 256, 4, 4, 16, 2, 1, 128};
    conv_zero(off2_w, 1024, skip1, off2_b, offb, 48, 1024, 16384, g2);
    dsample(skip1, offb, col, 64, 8, 256, 256, 4, 4, 2, 1, 128, 128);
    gemm_col(dcn2_w, 1024, col, dcn2_b, tmp, 128, 1024, 16384);
    fstats(128, 16384, 128);
    napply(tmp, skip2, 128, 16384, nullptr, 1);

    // ===== Stage 3: mdcp(h2, 4x4, s2, p1), 128 -> 256, 64x64 =====
    ConvGeom g3 = {128, 128, 128, 4, 4, 16, 2, 1, 64};
    conv_zero(off3_w, 2048, skip2, off3_b, offb, 48, 2048, 4096, g3);
    dsample(skip2, offb, col, 128, 8, 128, 128, 4, 4, 2, 1, 64, 64);
    gemm_col(dcn3_w, 2048, col, dcn3_b, tmp, 256, 2048, 4096);
    fstats(256, 4096, 32);
    napply(tmp, ga, 256, 4096, nullptr, 1);

    // ===== Res block 1: conv1 -> (stats) -> conv2 reads tmp with inline norm =====
    ConvGeom gr = {256, 64, 64, 3, 3, 9, 1, 1, 64};
    conv_refl(rb1_w1, 2304, ga, rb1_b1, tmp, 256, 2304, 4096, gr, false);
    fstats(256, 4096, 32);
    conv_refl(rb1_w2, 2304, tmp, rb1_b2, gb, 256, 2304, 4096, gr, true);
    fstats(256, 4096, 32);
    napply(gb, ga, 256, 4096, ga, 0);

    // ===== Res block 2 =====
    conv_refl(rb2_w1, 2304, ga, rb2_b1, tmp, 256, 2304, 4096, gr, false);
    fstats(256, 4096, 32);
    conv_refl(rb2_w2, 2304, tmp, rb2_b2, gb, 256, 2304, 4096, gr, true);
    fstats(256, 4096, 32);
    napply(gb, out_h, 256, 4096, ga, 0);
}

// round 17
// speedup vs baseline: 1.0032x; 1.0032x over previous
#include <cuda_runtime.h>
#include <cuda_fp16.h>
#include <math.h>
#include <stdint.h>

// ---------------- scratch (static device globals; no allocation) ----------------
__device__ float g_col[33554432];
__device__ float g_off[19267584];
__device__ float g_tmp[8388608];
__device__ float g_a[2097152];
__device__ float g_b[2097152];
__device__ float g_mean[512];
__device__ float g_rstd[512];
__device__ float g_wpad[33760];
__device__ float g_psum[262144];
__device__ float g_psum2[262144];

#define MAXCOL 512

// ---------------- deformable sampling -> col matrix (4 px/thread, channel-chunked) ----------------
__global__ void deform_sample_kernel(const float* __restrict__ x,
                                     const float* __restrict__ off,
                                     float* __restrict__ col,
                                     int Cin, int cchunk, int nChunk,
                                     int H, int W, int KH, int KW,
                                     int stride, int pad, int Ho, int Wo)
{
    int npix = Ho * Wo;
    int pix0 = (blockIdx.x * blockDim.x + threadIdx.x) * 4;
    if (pix0 >= npix) return;
    int K = KH * KW;
    int k = blockIdx.y;
    int n = blockIdx.z / nChunk;
    int c0 = (blockIdx.z % nChunk) * cchunk;

    const float* offn = off + (size_t)n * 3 * K * npix;
    float4 oy4 = *(const float4*)(offn + (size_t)k * npix + pix0);
    float4 ox4 = *(const float4*)(offn + (size_t)(K + k) * npix + pix0);
    float4 ml4 = *(const float4*)(offn + (size_t)(2 * K + k) * npix + pix0);
    float oys[4] = {oy4.x, oy4.y, oy4.z, oy4.w};
    float oxs[4] = {ox4.x, ox4.y, ox4.z, ox4.w};
    float mls[4] = {ml4.x, ml4.y, ml4.z, ml4.w};

    int ky = k / KW, kx = k % KW;
    float w00[4], w01[4], w10[4], w11[4];
    int b00[4], b01[4], b10[4], b11[4];
#pragma unroll
    for (int i = 0; i < 4; i++) {
        int pix = pix0 + i;
        int ho = pix / Wo, wo = pix % Wo;
        float m = 1.0f / (1.0f + expf(-mls[i]));
        float py = (float)(ho * stride - pad + ky) + oys[i];
        float px = (float)(wo * stride - pad + kx) + oxs[i];
        float y0f = floorf(py), x0f = floorf(px);
        int y0 = (int)y0f, x0 = (int)x0f;
        float wy = py - y0f, wx = px - x0f;
        int y1 = y0 + 1, x1 = x0 + 1;
        float vy0 = (y0 >= 0 && y0 <= H - 1) ? 1.0f : 0.0f;
        float vy1 = (y1 >= 0 && y1 <= H - 1) ? 1.0f : 0.0f;
        float vx0 = (x0 >= 0 && x0 <= W - 1) ? 1.0f : 0.0f;
        float vx1 = (x1 >= 0 && x1 <= W - 1) ? 1.0f : 0.0f;
        int y0c = min(max(y0, 0), H - 1), y1c = min(max(y1, 0), H - 1);
        int x0c = min(max(x0, 0), W - 1), x1c = min(max(x1, 0), W - 1);
        w00[i] = (1.0f - wy) * (1.0f - wx) * vy0 * vx0 * m;
        w01[i] = (1.0f - wy) * wx          * vy0 * vx1 * m;
        w10[i] = wy          * (1.0f - wx) * vy1 * vx0 * m;
        w11[i] = wy          * wx          * vy1 * vx1 * m;
        b00[i] = y0c * W + x0c;
        b01[i] = y0c * W + x1c;
        b10[i] = y1c * W + x0c;
        b11[i] = y1c * W + x1c;
    }

    const float* xn = x + (size_t)n * Cin * H * W;
    float* cp = col + (size_t)n * Cin * K * npix + (size_t)k * npix + pix0;
    size_t cstride = (size_t)K * npix;
    int cend = min(c0 + cchunk, Cin);
    for (int c = c0; c < cend; c++) {
        const float* xc = xn + (size_t)c * H * W;
        float4 v;
        v.x = w00[0] * __ldg(xc + b00[0]) + w01[0] * __ldg(xc + b01[0])
            + w10[0] * __ldg(xc + b10[0]) + w11[0] * __ldg(xc + b11[0]);
        v.y = w00[1] * __ldg(xc + b00[1]) + w01[1] * __ldg(xc + b01[1])
            + w10[1] * __ldg(xc + b10[1]) + w11[1] * __ldg(xc + b11[1]);
        v.z = w00[2] * __ldg(xc + b00[2]) + w01[2] * __ldg(xc + b01[2])
            + w10[2] * __ldg(xc + b10[2]) + w11[2] * __ldg(xc + b11[2]);
        v.w = w00[3] * __ldg(xc + b00[3]) + w01[3] * __ldg(xc + b01[3])
            + w10[3] * __ldg(xc + b10[3]) + w11[3] * __ldg(xc + b11[3]);
        *(float4*)(cp + (size_t)c * cstride) = v;
    }
}

// ---------------- fused stage-1 weight padding (off1 + dcn1, K=147 -> lda=160) ----------------
__global__ void pad_weights2_kernel(const float* __restrict__ w1, float* __restrict__ wp1, int M1,
                                    const float* __restrict__ w2, float* __restrict__ wp2, int M2,
                                    int K, int Kp)
{
    int idx = blockIdx.x * blockDim.x + threadIdx.x;
    int total1 = M1 * Kp;
    if (idx < total1) {
        int m = idx / Kp, k = idx % Kp;
        wp1[idx] = (k < K) ? w1[m * K + k] : 0.0f;
        return;
    }
    idx -= total1;
    if (idx < M2 * Kp) {
        int m = idx / Kp, k = idx % Kp;
        wp2[idx] = (k < K) ? w2[m * K + k] : 0.0f;
    }
}

// ---------------- fp16x3 implicit-conv / GEMM kernel (pre-split smem) ----------------
// MODE 0: B = col matrix;  MODE 1: implicit zero-pad conv;  MODE 2: reflect-pad (BNORM option)
struct ConvGeom { int Cin, H, W, KH, KW, KKW, stride, pad, Wo; };

__device__ __forceinline__ void split_h2(float a, float b, uint32_t& hi, uint32_t& lo) {
    __half ha = __float2half_rn(a), hb = __float2half_rn(b);
    float ra = a - __half2float(ha), rb = b - __half2float(hb);
    __half2 H = __halves2half2(ha, hb);
    __half2 L = __halves2half2(__float2half_rn(ra), __float2half_rn(rb));
    hi = *reinterpret_cast<uint32_t*>(&H);
    lo = *reinterpret_cast<uint32_t*>(&L);
}

#define AS2_STRIDE 20
#define BS2_STRIDE 136
#define BS2_BUF (16 * BS2_STRIDE)

extern __shared__ float smem_dyn[];

#define MMA_F16(acc, a0, a1, a2, a3, b0, b1)                                   \
    asm volatile(                                                              \
        "mma.sync.aligned.m16n8k16.row.col.f32.f16.f16.f32 "                   \
        "{%0,%1,%2,%3}, {%4,%5,%6,%7}, {%8,%9}, {%0,%1,%2,%3};\n"              \
        : "+f"(acc[0]), "+f"(acc[1]), "+f"(acc[2]), "+f"(acc[3])               \
        : "r"(a0), "r"(a1), "r"(a2), "r"(a3), "r"(b0), "r"(b1))

template <int BM, int MODE, bool STATS, bool BNORM>
__global__ void __launch_bounds__(256, 1)
gemm_conv_kernel(const float* __restrict__ A, int lda,
                 const float* __restrict__ B,
                 const float* __restrict__ bias,
                 float* __restrict__ C,
                 int M, int Kd, int N, ConvGeom g,
                 float* __restrict__ psum, float* __restrict__ psum2,
                 const float* __restrict__ nmean, const float* __restrict__ nrstd)
{
    constexpr int AS2_BUF = BM * AS2_STRIDE;
    constexpr int IMAX = BM / 32;
    constexpr int ACP = BM / 32;
    uint32_t* AsH = (uint32_t*)smem_dyn;
    uint32_t* AsL = AsH + 2 * AS2_BUF;
    uint32_t* BsH = AsL + 2 * AS2_BUF;
    uint32_t* BsL = BsH + 2 * BS2_BUF;
    constexpr int SW = STATS ? 4 : 1;
    __shared__ float s_sum[SW][BM][2];

    int nb = blockIdx.z;
    float* Cn = C + (size_t)nb * M * N;
    int bm = blockIdx.y * BM, bn = blockIdx.x * 128;
    int tid = threadIdx.x;
    int wid = tid >> 5, lane = tid & 31;
    int warp_m = (wid >> 2) * (BM / 2);
    int warp_n = (wid & 3) * 32;
    int lr = lane >> 2, lc = lane & 3;

    float acc[IMAX][4][4];
#pragma unroll
    for (int i = 0; i < IMAX; i++)
#pragma unroll
        for (int j = 0; j < 4; j++)
#pragma unroll
            for (int q = 0; q < 4; q++) acc[i][j][q] = 0.0f;

    int nk = (Kd + 31) / 32;

    auto loadA = [&](int kt, float4* apref) {
        int k0 = kt * 32;
#pragma unroll
        for (int t = 0; t < ACP; t++) {
            int idx = tid + t * 256;
            int m = idx >> 3;
            int k4 = (idx & 7) << 2;
            int gm = bm + m;
            if (gm < M) apref[t] = *(const float4*)(A + (size_t)gm * lda + k0 + k4);
            else        apref[t] = make_float4(0.f, 0.f, 0.f, 0.f);
        }
    };
    auto stsA = [&](const float4* apref, int s) {
        uint32_t* dH = AsH + s * AS2_BUF;
        uint32_t* dL = AsL + s * AS2_BUF;
#pragma unroll
        for (int t = 0; t < ACP; t++) {
            int idx = tid + t * 256;
            int m = idx >> 3;
            int kp = (idx & 7) << 1;
            uint32_t h0, l0, h1, l1;
            split_h2(apref[t].x, apref[t].y, h0, l0);
            split_h2(apref[t].z, apref[t].w, h1, l1);
            dH[m * AS2_STRIDE + kp] = h0; dH[m * AS2_STRIDE + kp + 1] = h1;
            dL[m * AS2_STRIDE + kp] = l0; dL[m * AS2_STRIDE + kp + 1] = l1;
        }
    };

    int kp_t = tid >> 4;
    int cb_t = (tid & 15) << 3;

    auto loadB_col = [&](int kt, float* r0, float* r1) {
        const float* Bn = B + (size_t)nb * Kd * N;
        int gk0 = kt * 32 + 2 * kp_t;
        int gk1 = gk0 + 1;
        if (gk0 < Kd) {
            float4 a = *(const float4*)(Bn + (size_t)gk0 * N + bn + cb_t);
            float4 b = *(const float4*)(Bn + (size_t)gk0 * N + bn + cb_t + 4);
            r0[0]=a.x; r0[1]=a.y; r0[2]=a.z; r0[3]=a.w; r0[4]=b.x; r0[5]=b.y; r0[6]=b.z; r0[7]=b.w;
        } else { for (int i = 0; i < 8; i++) r0[i] = 0.0f; }
        if (gk1 < Kd) {
            float4 a = *(const float4*)(Bn + (size_t)gk1 * N + bn + cb_t);
            float4 b = *(const float4*)(Bn + (size_t)gk1 * N + bn + cb_t + 4);
            r1[0]=a.x; r1[1]=a.y; r1[2]=a.z; r1[3]=a.w; r1[4]=b.x; r1[5]=b.y; r1[6]=b.z; r1[7]=b.w;
        } else { for (int i = 0; i < 8; i++) r1[i] = 0.0f; }
    };

    auto gatherB_row = [&](int gk, float* r) {
        bool kv = gk < Kd;
        int kk = kv ? gk : 0;
        int c = kk / g.KKW;
        int rr = kk - c * g.KKW;
        int ky = rr / g.KW;
        int kx = rr - ky * g.KW;
        int pix = bn + cb_t;
        int ho = pix / g.Wo;
        int wo = pix - ho * g.Wo;
        int iy = ho * g.stride - g.pad + ky;
        int ix0 = wo * g.stride - g.pad + kx;
        const float* xc = B + ((size_t)nb * g.Cin + c) * g.H * g.W;
        if (MODE == 2) {
            float mnv = 0.0f, rsv = 1.0f;
            if (BNORM) {
                mnv = __ldg(nmean + nb * g.Cin + c);
                rsv = __ldg(nrstd + nb * g.Cin + c);
            }
            if (iy < 0) iy = -iy; else if (iy >= g.H) iy = 2 * g.H - 2 - iy;
            const float* rowp = xc + (size_t)iy * g.W;
#pragma unroll
            for (int i = 0; i < 8; i++) {
                int ix = ix0 + i * g.stride;
                if (ix < 0) ix = -ix; else if (ix >= g.W) ix = 2 * g.W - 2 - ix;
                float v = kv ? __ldg(rowp + ix) : 0.0f;
                if (BNORM) v = fmaxf((v - mnv) * rsv, 0.0f);
                r[i] = v;
            }
        } else {
            bool rok = kv && iy >= 0 && iy < g.H;
            const float* rowp = xc + (size_t)max(iy, 0) * g.W;
#pragma unroll
            for (int i = 0; i < 8; i++) {
                int ix = ix0 + i * g.stride;
                r[i] = (rok && ix >= 0 && ix < g.W) ? __ldg(rowp + ix) : 0.0f;
            }
        }
    };
    auto loadB = [&](int kt, float* r0, float* r1) {
        if (MODE == 0) { loadB_col(kt, r0, r1); }
        else {
            int gk0 = kt * 32 + 2 * kp_t;
            gatherB_row(gk0, r0);
            gatherB_row(gk0 + 1, r1);
        }
    };
    auto stsB = [&](const float* r0, const float* r1, int s) {
        uint32_t* dH = BsH + s * BS2_BUF + kp_t * BS2_STRIDE + cb_t;
        uint32_t* dL = BsL + s * BS2_BUF + kp_t * BS2_STRIDE + cb_t;
#pragma unroll
        for (int i = 0; i < 8; i++) {
            uint32_t h, l;
            split_h2(r0[i], r1[i], h, l);
            dH[i] = h; dL[i] = l;
        }
    };

    float4 apref[ACP];
    float br0[8], br1[8];
    loadA(0, apref);
    loadB(0, br0, br1);
    stsA(apref, 0);
    stsB(br0, br1, 0);
    __syncthreads();

    for (int kt = 0; kt < nk; kt++) {
        int s = kt & 1;
        bool do_pref = (kt + 1 < nk);
        if (do_pref) {
            loadA(kt + 1, apref);
            loadB(kt + 1, br0, br1);
        }

        const uint32_t* AsHb = AsH + s * AS2_BUF;
        const uint32_t* AsLb = AsL + s * AS2_BUF;
        const uint32_t* BsHb = BsH + s * BS2_BUF;
        const uint32_t* BsLb = BsL + s * BS2_BUF;
#pragma unroll
        for (int ks = 0; ks < 2; ks++) {
            uint32_t ah[IMAX][4], al[IMAX][4], bh[4][2], bl[4][2];
#pragma unroll
            for (int i = 0; i < IMAX; i++) {
                int base = (warp_m + i * 16 + lr) * AS2_STRIDE + ks * 8 + lc;
                ah[i][0] = AsHb[base];
                ah[i][1] = AsHb[base + 8 * AS2_STRIDE];
                ah[i][2] = AsHb[base + 4];
                ah[i][3] = AsHb[base + 8 * AS2_STRIDE + 4];
                al[i][0] = AsLb[base];
                al[i][1] = AsLb[base + 8 * AS2_STRIDE];
                al[i][2] = AsLb[base + 4];
                al[i][3] = AsLb[base + 8 * AS2_STRIDE + 4];
            }
#pragma unroll
            for (int j = 0; j < 4; j++) {
                int bbase = (ks * 8 + lc) * BS2_STRIDE + warp_n + j * 8 + lr;
                bh[j][0] = BsHb[bbase];
                bh[j][1] = BsHb[bbase + 4 * BS2_STRIDE];
                bl[j][0] = BsLb[bbase];
                bl[j][1] = BsLb[bbase + 4 * BS2_STRIDE];
            }
#pragma unroll
            for (int i = 0; i < IMAX; i++)
#pragma unroll
                for (int j = 0; j < 4; j++) {
                    MMA_F16(acc[i][j], ah[i][0], ah[i][1], ah[i][2], ah[i][3],
                            bl[j][0], bl[j][1]);
                    MMA_F16(acc[i][j], al[i][0], al[i][1], al[i][2], al[i][3],
                            bh[j][0], bh[j][1]);
                    MMA_F16(acc[i][j], ah[i][0], ah[i][1], ah[i][2], ah[i][3],
                            bh[j][0], bh[j][1]);
                }
        }
        if (do_pref) {
            stsA(apref, s ^ 1);
            stsB(br0, br1, s ^ 1);
        }
        __syncthreads();
    }

#pragma unroll
    for (int i = 0; i < IMAX; i++) {
        int r0l = warp_m + i * 16 + lr;
        int r1l = r0l + 8;
        int gr0 = bm + r0l, gr1 = bm + r1l;
        float bv0 = (gr0 < M) ? bias[gr0] : 0.0f;
        float bv1 = (gr1 < M) ? bias[gr1] : 0.0f;
        float s0 = 0, q0 = 0, s1 = 0, q1 = 0;
#pragma unroll
        for (int j = 0; j < 4; j++) {
            int cidx = bn + warp_n + j * 8 + lc * 2;
            float v0 = acc[i][j][0] + bv0, v1 = acc[i][j][1] + bv0;
            float v2 = acc[i][j][2] + bv1, v3 = acc[i][j][3] + bv1;
            if (gr0 < M) *(float2*)&Cn[(size_t)gr0 * N + cidx] = make_float2(v0, v1);
            if (gr1 < M) *(float2*)&Cn[(size_t)gr1 * N + cidx] = make_float2(v2, v3);
            if (STATS) {
                s0 += v0 + v1; q0 += v0 * v0 + v1 * v1;
                s1 += v2 + v3; q1 += v2 * v2 + v3 * v3;
            }
        }
        if (STATS) {
            s0 += __shfl_xor_sync(0xffffffff, s0, 1); s0 += __shfl_xor_sync(0xffffffff, s0, 2);
            q0 += __shfl_xor_sync(0xffffffff, q0, 1); q0 += __shfl_xor_sync(0xffffffff, q0, 2);
            s1 += __shfl_xor_sync(0xffffffff, s1, 1); s1 += __shfl_xor_sync(0xffffffff, s1, 2);
            q1 += __shfl_xor_sync(0xffffffff, q1, 1); q1 += __shfl_xor_sync(0xffffffff, q1, 2);
            if (lc == 0) {
                s_sum[wid & 3][r0l][0] = s0; s_sum[wid & 3][r0l][1] = q0;
                s_sum[wid & 3][r1l][0] = s1; s_sum[wid & 3][r1l][1] = q1;
            }
        }
    }
    if (STATS) {
        __syncthreads();
        if (tid < BM) {
            int gm = bm + tid;
            if (gm < M) {
                float s = s_sum[0][tid][0] + s_sum[1][tid][0] + s_sum[2][tid][0] + s_sum[3][tid][0];
                float q = s_sum[0][tid][1] + s_sum[1][tid][1] + s_sum[2][tid][1] + s_sum[3][tid][1];
                size_t nc = (size_t)nb * M + gm;
                psum[nc * MAXCOL + blockIdx.x] = s;
                psum2[nc * MAXCOL + blockIdx.x] = q;
            }
        }
    }
}

// ---------------- finalize stats ----------------
__global__ void finalize_stats_kernel(const float* __restrict__ ps,
                                      const float* __restrict__ ps2,
                                      float* __restrict__ mean, float* __restrict__ rstd,
                                      int ncol, int npix)
{
    int nc = blockIdx.x;
    double s = 0.0, s2 = 0.0;
    for (int j = threadIdx.x; j < ncol; j += 128) {
        s += (double)ps[(size_t)nc * MAXCOL + j];
        s2 += (double)ps2[(size_t)nc * MAXCOL + j];
    }
    __shared__ double sh[128], sh2[128];
    sh[threadIdx.x] = s; sh2[threadIdx.x] = s2;
    __syncthreads();
    for (int o = 64; o > 0; o >>= 1) {
        if (threadIdx.x < o) { sh[threadIdx.x] += sh[threadIdx.x + o]; sh2[threadIdx.x] += sh2[threadIdx.x + o]; }
        __syncthreads();
    }
    if (threadIdx.x == 0) {
        double mn = sh[0] / npix;
        double var = sh2[0] / npix - mn * mn;
        mean[nc] = (float)mn;
        rstd[nc] = (float)rsqrt(var + 1e-5);
    }
}

// ---------------- instance norm: apply (float4) ----------------
__global__ void norm_apply_kernel(const float4* __restrict__ x,
                                  const float* __restrict__ mean,
                                  const float* __restrict__ rstd,
                                  const float4* __restrict__ skip,
                                  float4* __restrict__ out,
                                  int npix4, int relu, size_t total4)
{
    size_t i = (size_t)blockIdx.x * blockDim.x + threadIdx.x;
    if (i >= total4) return;
    int nc = (int)(i / (size_t)npix4);
    float mnv = mean[nc], rsv = rstd[nc];
    float4 v = x[i];
    v.x = (v.x - mnv) * rsv; v.y = (v.y - mnv) * rsv;
    v.z = (v.z - mnv) * rsv; v.w = (v.w - mnv) * rsv;
    if (skip) {
        float4 sk = skip[i];
        v.x += sk.x; v.y += sk.y; v.z += sk.z; v.w += sk.w;
    }
    if (relu) {
        v.x = fmaxf(v.x, 0.0f); v.y = fmaxf(v.y, 0.0f);
        v.z = fmaxf(v.z, 0.0f); v.w = fmaxf(v.w, 0.0f);
    }
    out[i] = v;
}

// ---------------- launch ----------------
static inline int smem_for(int BM) { return (4 * BM * AS2_STRIDE + 4 * BS2_BUF) * 4; }

extern "C" void kernel_launch(void* const* d_in, const int* in_sizes, int n_in,
                              void* d_out, int out_size)
{
    (void)in_sizes; (void)n_in; (void)out_size;
    const float* x      = (const float*)d_in[0];
    const float* off1_w = (const float*)d_in[1];
    const float* off1_b = (const float*)d_in[2];
    const float* dcn1_w = (const float*)d_in[3];
    const float* dcn1_b = (const float*)d_in[4];
    const float* off2_w = (const float*)d_in[5];
    const float* off2_b = (const float*)d_in[6];
    const float* dcn2_w = (const float*)d_in[7];
    const float* dcn2_b = (const float*)d_in[8];
    const float* off3_w = (const float*)d_in[9];
    const float* off3_b = (const float*)d_in[10];
    const float* dcn3_w = (const float*)d_in[11];
    const float* dcn3_b = (const float*)d_in[12];
    const float* rb1_w1 = (const float*)d_in[13];
    const float* rb1_b1 = (const float*)d_in[14];
    const float* rb1_w2 = (const float*)d_in[15];
    const float* rb1_b2 = (const float*)d_in[16];
    const float* rb2_w1 = (const float*)d_in[17];
    const float* rb2_b1 = (const float*)d_in[18];
    const float* rb2_w2 = (const float*)d_in[19];
    const float* rb2_b2 = (const float*)d_in[20];

    float* outp  = (float*)d_out;
    float* out_h = outp;
    float* skip1 = outp + 2097152;
    float* skip2 = outp + 2097152 + 8388608;

    float *col, *offb, *tmp, *ga, *gb, *mn, *rs, *wpad, *psum, *psum2;
    cudaGetSymbolAddress((void**)&col,  g_col);
    cudaGetSymbolAddress((void**)&offb, g_off);
    cudaGetSymbolAddress((void**)&tmp,  g_tmp);
    cudaGetSymbolAddress((void**)&ga,   g_a);
    cudaGetSymbolAddress((void**)&gb,   g_b);
    cudaGetSymbolAddress((void**)&mn,   g_mean);
    cudaGetSymbolAddress((void**)&rs,   g_rstd);
    cudaGetSymbolAddress((void**)&wpad, g_wpad);
    cudaGetSymbolAddress((void**)&psum, g_psum);
    cudaGetSymbolAddress((void**)&psum2, g_psum2);
    float* off1p = wpad;
    float* dcn1p = wpad + 147 * 160;

    static bool attr_set = false;
    if (!attr_set) {
        cudaFuncSetAttribute((const void*)gemm_conv_kernel<64, 0, true, false>,   cudaFuncAttributeMaxDynamicSharedMemorySize, smem_for(64));
        cudaFuncSetAttribute((const void*)gemm_conv_kernel<128, 0, true, false>,  cudaFuncAttributeMaxDynamicSharedMemorySize, smem_for(128));
        cudaFuncSetAttribute((const void*)gemm_conv_kernel<64, 1, false, false>,  cudaFuncAttributeMaxDynamicSharedMemorySize, smem_for(64));
        cudaFuncSetAttribute((const void*)gemm_conv_kernel<128, 2, true, false>,  cudaFuncAttributeMaxDynamicSharedMemorySize, smem_for(128));
        cudaFuncSetAttribute((const void*)gemm_conv_kernel<128, 2, true, true>,   cudaFuncAttributeMaxDynamicSharedMemorySize, smem_for(128));
        attr_set = true;
    }

    ConvGeom g0 = {};

    auto dsample = [&](const float* src, const float* off, float* dst, int Cin, int cchunk,
                       int H, int W, int KH, int KW, int s, int p, int Ho, int Wo) {
        int npix4 = Ho * Wo / 4;
        int nChunk = (Cin + cchunk - 1) / cchunk;
        dim3 grid((npix4 + 255) / 256, KH * KW, 2 * nChunk);
        deform_sample_kernel<<<grid, 256>>>(src, off, dst, Cin, cchunk, nChunk,
                                            H, W, KH, KW, s, p, Ho, Wo);
    };
    auto gemm_col = [&](const float* W, int lda, const float* B, const float* bias, float* C,
                        int M, int K, int N) {
        if (M <= 64) {
            dim3 grid(N / 128, 1, 2);
            gemm_conv_kernel<64, 0, true, false><<<grid, 256, smem_for(64)>>>(
                W, lda, B, bias, C, M, K, N, g0, psum, psum2, nullptr, nullptr);
        } else {
            dim3 grid(N / 128, (M + 127) / 128, 2);
            gemm_conv_kernel<128, 0, true, false><<<grid, 256, smem_for(128)>>>(
                W, lda, B, bias, C, M, K, N, g0, psum, psum2, nullptr, nullptr);
        }
    };
    auto conv_zero = [&](const float* W, int lda, const float* X, const float* bias, float* C,
                         int M, int K, int N, ConvGeom g) {
        dim3 grid(N / 128, (M + 63) / 64, 2);
        gemm_conv_kernel<64, 1, false, false><<<grid, 256, smem_for(64)>>>(
            W, lda, X, bias, C, M, K, N, g, nullptr, nullptr, nullptr, nullptr);
    };
    auto conv_refl = [&](const float* W, int lda, const float* X, const float* bias, float* C,
                         int M, int K, int N, ConvGeom g, bool bnorm) {
        dim3 grid(N / 128, (M + 127) / 128, 2);
        if (bnorm)
            gemm_conv_kernel<128, 2, true, true><<<grid, 256, smem_for(128)>>>(
                W, lda, X, bias, C, M, K, N, g, psum, psum2, mn, rs);
        else
            gemm_conv_kernel<128, 2, true, false><<<grid, 256, smem_for(128)>>>(
                W, lda, X, bias, C, M, K, N, g, psum, psum2, nullptr, nullptr);
    };
    auto fstats = [&](int C, int npix, int ncol) {
        finalize_stats_kernel<<<2 * C, 128>>>(psum, psum2, mn, rs, ncol, npix);
    };
    auto napply = [&](const float* xin, float* dst, int C, int npix,
                      const float* skip, int relu) {
        size_t total4 = (size_t)2 * C * npix / 4;
        norm_apply_kernel<<<(unsigned)((total4 + 255) / 256), 256>>>(
            (const float4*)xin, mn, rs, (const float4*)skip, (float4*)dst, npix / 4, relu, total4);
    };

    // pack stage-1 weights (fused: off1 + dcn1, K=147 -> lda=160)
    pad_weights2_kernel<<<((147 + 64) * 160 + 255) / 256, 256>>>(
        off1_w, off1p, 147, dcn1_w, dcn1p, 64, 147, 160);

    // ===== Stage 1: mdcp(x, 7x7, s1, p3), 3 -> 64, 256x256 =====
    ConvGeom g1 = {3, 256, 256, 7, 7, 49, 1, 3, 256};
    conv_zero(off1p, 160, x, off1_b, offb, 147, 147, 65536, g1);
    dsample(x, offb, col, 3, 3, 256, 256, 7, 7, 1, 3, 256, 256);
    gemm_col(dcn1p, 160, col, dcn1_b, tmp, 64, 147, 65536);
    fstats(64, 65536, 512);
    napply(tmp, skip1, 64, 65536, nullptr, 1);

    // ===== Stage 2: mdcp(h1, 4x4, s2, p1), 64 -> 128, 128x128 =====
    ConvGeom g2 = {64, 256, 256, 4, 4, 16, 2, 1, 128};
    conv_zero(off2_w, 1024, skip1, off2_b, offb, 48, 1024, 16384, g2);
    dsample(skip1, offb, col, 64, 8, 256, 256, 4, 4, 2, 1, 128, 128);
    gemm_col(dcn2_w, 1024, col, dcn2_b, tmp, 128, 1024, 16384);
    fstats(128, 16384, 128);
    napply(tmp, skip2, 128, 16384, nullptr, 1);

    // ===== Stage 3: mdcp(h2, 4x4, s2, p1), 128 -> 256, 64x64 =====
    ConvGeom g3 = {128, 128, 128, 4, 4, 16, 2, 1, 64};
    conv_zero(off3_w, 2048, skip2, off3_b, offb, 48, 2048, 4096, g3);
    dsample(skip2, offb, col, 128, 8, 128, 128, 4, 4, 2, 1, 64, 64);
    gemm_col(dcn3_w, 2048, col, dcn3_b, tmp, 256, 2048, 4096);
    fstats(256, 4096, 32);
    napply(tmp, ga, 256, 4096, nullptr, 1);

    // ===== Res block 1: conv1 -> (stats) -> conv2 reads tmp with inline norm =====
    ConvGeom gr = {256, 64, 64, 3, 3, 9, 1, 1, 64};
    conv_refl(rb1_w1, 2304, ga, rb1_b1, tmp, 256, 2304, 4096, gr, false);
    fstats(256, 4096, 32);
    conv_refl(rb1_w2, 2304, tmp, rb1_b2, gb, 256, 2304, 4096, gr, true);
    fstats(256, 4096, 32);
    napply(gb, ga, 256, 4096, ga, 0);

    // ===== Res block 2 =====
    conv_refl(rb2_w1, 2304, ga, rb2_b1, tmp, 256, 2304, 4096, gr, false);
    fstats(256, 4096, 32);
    conv_refl(rb2_w2, 2304, tmp, rb2_b2, gb, 256, 2304, 4096, gr, true);
    fstats(256, 4096, 32);
    napply(gb, out_h, 256, 4096, ga, 0);
}